// round 13
// baseline (speedup 1.0000x reference)
#include <cuda_runtime.h>
#include <cuda_bf16.h>

// SSIM loss, fully fused. (1,3,2048,2048) fp32, VALID 11-tap separable Gaussian
// (sigma=1.5). Output scalar fp32 = 1 - mean(ssim_map) over (3,2038,2038).
//
// v13 = v12 with TILE_H=54 (IN_H=64): phase A = 64 rows x 4 runs = 256 tasks
// = EXACTLY 2 full passes of 128 threads (100% util, was 66%), -10% vertical
// halo, -41% blocks. Phase B: 54 rows as 13/13/14/14 per warp, chunked 8+5/6
// rows to keep the proven register profile. Tail byte-identical (padded
// g_partial).

#define H_DIM 2048
#define W_DIM 2048
#define OUT_DIM 2038
#define TILE_W 32
#define TILE_H 54
#define IN_H 64
#define NTHREADS 128
#define HB_STRIDE 36
#define GRID_X 64
#define GRID_Y 38            // 38*54 = 2052 >= 2038
#define NBLOCKS_PAD 12288    // g_partial padded; unwritten slots stay 0.0

// Normalized gaussian(sigma=1.5, size=11); sum == 1.0f exactly.
#define W0 0.00102841f
#define W1 0.00759878f
#define W2 0.03600077f
#define W3 0.10936067f
#define W4 0.21300553f
#define W5 0.26601168f

__device__ float g_partial[NBLOCKS_PAD];

// NOUT 11-tap dot products over an (NOUT+10)-wide window; FFMA-imm weights.
template <int NOUT>
__device__ __forceinline__ void convN(const float* __restrict__ v,
                                      float* __restrict__ acc) {
    const float W[11] = {W0, W1, W2, W3, W4, W5, W4, W3, W2, W1, W0};
    #pragma unroll
    for (int j = 0; j < NOUT; ++j) {
        float a = W0 * v[j];
        #pragma unroll
        for (int t = 1; t < 11; ++t)
            a = fmaf(W[t], v[j + t], a);
        acc[j] = a;
    }
}

__device__ __forceinline__ void load18(const float* __restrict__ p,
                                       float* __restrict__ v) {
    // p is 32B-aligned. 4xLDG.128 + 1xLDG.64.
    #pragma unroll
    for (int k = 0; k < 4; ++k) {
        float4 q = __ldg(reinterpret_cast<const float4*>(p) + k);
        v[4 * k + 0] = q.x; v[4 * k + 1] = q.y;
        v[4 * k + 2] = q.z; v[4 * k + 3] = q.w;
    }
    float2 q2 = __ldg(reinterpret_cast<const float2*>(p) + 8);
    v[16] = q2.x; v[17] = q2.y;
}

__device__ __forceinline__ void store8(float* __restrict__ dst,
                                       const float* __restrict__ a) {
    float4* d4 = reinterpret_cast<float4*>(dst);
    d4[0] = make_float4(a[0], a[1], a[2], a[3]);
    d4[1] = make_float4(a[4], a[5], a[6], a[7]);
}

// Vertical-blur + SSIM for NR output rows starting at local row r0.
template <int NR>
__device__ __forceinline__ float ssim_rows(const float hb[4][IN_H][HB_STRIDE],
                                           int r0, int tx, int gy0, int ox) {
    float v[NR + 10];
    float acc[4][NR];
    #pragma unroll
    for (int m = 0; m < 4; ++m) {
        #pragma unroll
        for (int k = 0; k < NR + 10; ++k) v[k] = hb[m][r0 + k][tx];
        convN<NR>(v, acc[m]);
    }
    const float C1 = 0.01f * 0.01f;
    const float C2 = 0.03f * 0.03f;
    float lsum = 0.0f;
    #pragma unroll
    for (int j = 0; j < NR; ++j) {
        int oy = gy0 + r0 + j;
        if (oy < OUT_DIM && ox < OUT_DIM) {
            float mu1 = acc[0][j], mu2 = acc[1][j];
            float P   = acc[2][j], Q   = acc[3][j];
            float m11 = mu1 * mu1;
            float m22 = mu2 * mu2;
            float m12 = mu1 * mu2;
            float num = (2.0f * m12 + C1) * (0.5f * (P - Q) - 2.0f * m12 + C2);
            float den = (m11 + m22 + C1) * (0.5f * (P + Q) - m11 - m22 + C2);
            lsum += __fdividef(num, den);
        }
    }
    return lsum;
}

__global__ __launch_bounds__(NTHREADS, 6)
void ssim_main_kernel(const float* __restrict__ xin, const float* __restrict__ yin) {
    __shared__ float hb[4][IN_H][HB_STRIDE];   // 36 KB
    __shared__ float red[4];

    const int tid = threadIdx.x;
    const int gx0 = blockIdx.x * TILE_W;
    const int gy0 = blockIdx.y * TILE_H;
    const float* __restrict__ xp = xin + (size_t)blockIdx.z * (H_DIM * W_DIM);
    const float* __restrict__ yp = yin + (size_t)blockIdx.z * (H_DIM * W_DIM);
    const bool interior = (blockIdx.x < GRID_X - 1) && (gy0 + IN_H <= H_DIM);

    // ---- Phase A: horizontal blur of 4 maps (x, y, (x+y)^2, (x-y)^2) ----
    // 64 rows x 4 runs of 8 cols = 256 tasks = exactly 2 full passes.
    #pragma unroll
    for (int pass = 0; pass < 2; ++pass) {
        int task = pass * NTHREADS + tid;
        int r  = task >> 2;
        int c0 = (task & 3) << 3;
        int gr = gy0 + r;
        int gc0 = gx0 + c0;
        float xw[18], yw[18], pw[18], acc[8];

        if (interior) {
            const float* xr = xp + (size_t)gr * W_DIM + gc0;
            const float* yr = yp + (size_t)gr * W_DIM + gc0;
            load18(xr, xw);
            load18(yr, yw);
        } else {
            #pragma unroll
            for (int k = 0; k < 18; ++k) {
                int gc = gc0 + k;
                bool ok = (gr < H_DIM) && (gc < W_DIM);
                int idx = gr * W_DIM + gc;
                xw[k] = ok ? __ldg(xp + idx) : 0.0f;
                yw[k] = ok ? __ldg(yp + idx) : 0.0f;
            }
        }

        convN<8>(xw, acc);
        store8(&hb[0][r][c0], acc);

        convN<8>(yw, acc);
        store8(&hb[1][r][c0], acc);

        #pragma unroll
        for (int k = 0; k < 18; ++k) {
            float u = xw[k] + yw[k];
            pw[k] = u * u;
        }
        convN<8>(pw, acc);
        store8(&hb[2][r][c0], acc);

        #pragma unroll
        for (int k = 0; k < 18; ++k) {
            float d = xw[k] - yw[k];
            pw[k] = d * d;
        }
        convN<8>(pw, acc);
        store8(&hb[3][r][c0], acc);
    }
    __syncthreads();

    // ---- Phase B: vertical blur + SSIM; 54 rows = 13/13/14/14 per warp,
    // chunked 8 + 5/6 to bound register pressure ----
    const int tx  = tid & 31;          // output column
    const int tg  = tid >> 5;          // warp id
    const int ox  = gx0 + tx;

    float lsum;
    if (tg < 2) {
        int r0 = tg * 13;
        lsum  = ssim_rows<8>(hb, r0,     tx, gy0, ox);
        lsum += ssim_rows<5>(hb, r0 + 8, tx, gy0, ox);
    } else {
        int r0 = 26 + (tg - 2) * 14;
        lsum  = ssim_rows<8>(hb, r0,     tx, gy0, ox);
        lsum += ssim_rows<6>(hb, r0 + 8, tx, gy0, ox);
    }

    #pragma unroll
    for (int off = 16; off > 0; off >>= 1)
        lsum += __shfl_down_sync(0xffffffffu, lsum, off);
    if (tx == 0) red[tg] = lsum;
    __syncthreads();
    if (tid == 0) {
        int bid = (blockIdx.z * GRID_Y + blockIdx.y) * GRID_X + blockIdx.x;
        g_partial[bid] = red[0] + red[1] + red[2] + red[3];
    }
}

// Tail: 1024 threads; fixed-order fp32 partial sums + shuffle tree -> replay-
// deterministic; double only for the final combine. Reads the padded array
// (unwritten slots are always 0).
__global__ __launch_bounds__(1024)
void ssim_final_kernel(float* __restrict__ out) {
    __shared__ double s[32];
    const int t = threadIdx.x;
    const float4* p = reinterpret_cast<const float4*>(g_partial);  // 3072 float4
    float4 a = p[t];
    float4 b = p[t + 1024];
    float4 c = p[t + 2048];
    float fs = ((a.x + a.y) + (a.z + a.w))
             + ((b.x + b.y) + (b.z + b.w))
             + ((c.x + c.y) + (c.z + c.w));
    double sum = (double)fs;
    #pragma unroll
    for (int off = 16; off > 0; off >>= 1)
        sum += __shfl_down_sync(0xffffffffu, sum, off);
    int lane = t & 31, wid = t >> 5;
    if (lane == 0) s[wid] = sum;
    __syncthreads();
    if (wid == 0) {
        double v = s[lane];
        #pragma unroll
        for (int off = 16; off > 0; off >>= 1)
            v += __shfl_down_sync(0xffffffffu, v, off);
        if (lane == 0) {
            double n = 3.0 * (double)OUT_DIM * (double)OUT_DIM;
            out[0] = 1.0f - (float)(v / n);
        }
    }
}

extern "C" void kernel_launch(void* const* d_in, const int* in_sizes, int n_in,
                              void* d_out, int out_size) {
    const float* pred = (const float*)d_in[0];
    const float* targ = (const float*)d_in[1];
    float* out = (float*)d_out;

    dim3 grid(GRID_X, GRID_Y, 3);
    ssim_main_kernel<<<grid, NTHREADS>>>(pred, targ);
    ssim_final_kernel<<<1, 1024>>>(out);
}